// round 1
// baseline (speedup 1.0000x reference)
#include <cuda_runtime.h>

// StreamingPCEN: x[B=16, MICS=4, T=2048, F=257] fp32.
// EMA over T per (bm, f) lane, then (x/(M+eps)^alpha + delta)^r - delta^r.
//
// Parallelization: 64 bm * 257 f = 16448 lanes = 514 warps.
// Grid: 16 bm-groups x 9 f-chunks = 144 blocks of 128 threads (4 warps, one bm
// each, 32 f-lanes each). One block per SM, one warp per SMSP, single wave.
// Per-warp software pipeline: chunks of U=32 t-steps, double-buffered register
// prefetch (32 LDGs in flight) to cover DRAM latency with 1 warp/SMSP.

#define TT   2048
#define FFR  257
#define NFC  9      // ceil(257/32)
#define U    32
#define NCH  (TT / U)   // 64
#define PCEN_EPS 1e-6f

__device__ __forceinline__ float fast_lg2(float a) {
    float r; asm("lg2.approx.f32 %0, %1;" : "=f"(r) : "f"(a)); return r;
}
__device__ __forceinline__ float fast_ex2(float a) {
    float r; asm("ex2.approx.f32 %0, %1;" : "=f"(r) : "f"(a)); return r;
}

__global__ __launch_bounds__(128)
void pcen_kernel(const float* __restrict__ x,
                 const float* __restrict__ s_p,
                 const float* __restrict__ a_p,
                 const float* __restrict__ d_p,
                 const float* __restrict__ r_p,
                 float* __restrict__ out)
{
    const int fc   = blockIdx.x % NFC;
    const int bg   = blockIdx.x / NFC;
    const int w    = threadIdx.x >> 5;
    const int lane = threadIdx.x & 31;
    const int bm   = bg * 4 + w;
    const int f    = fc * 32 + lane;
    const bool act = (f < FFR);
    const int fcl  = act ? f : (FFR - 1);   // clamp loads for inactive lanes

    const float s     = __ldg(s_p);
    const float alpha = __ldg(a_p);
    const float delta = __ldg(d_p);
    const float r     = __ldg(r_p);
    const float oms   = 1.0f - s;
    const float na    = -alpha;
    const float dr    = fast_ex2(r * fast_lg2(delta));   // delta^r

    const float* lp = x   + (size_t)bm * TT * FFR + fcl;  // load cursor
    float*       sp = out + (size_t)bm * TT * FFR + f;    // store cursor

    float bufA[U], bufB[U];

    // Prologue: load chunk 0 into A.
    #pragma unroll
    for (int i = 0; i < U; i++) bufA[i] = __ldg(lp + i * FFR);
    lp += U * FFR;

    // EMA state. Init so that applying the update at t=0 yields ~x0:
    // fma(1-s, x0, s*x0) = x0 * ((1-s)+s) = x0 (to within 1 ulp).
    float m = bufA[0];

    #pragma unroll 1
    for (int c = 0; c < NCH; c += 2) {
        // Prefetch chunk c+1 into B (always valid: c <= NCH-2).
        #pragma unroll
        for (int i = 0; i < U; i++) bufB[i] = __ldg(lp + i * FFR);
        lp += U * FFR;

        // Process chunk c from A.
        #pragma unroll
        for (int i = 0; i < U; i++) {
            const float xv = bufA[i];
            m = fmaf(oms, m, s * xv);
            const float e  = fast_ex2(na * fast_lg2(m + PCEN_EPS)); // (M+eps)^-alpha
            const float v  = fmaf(xv, e, delta);
            const float o  = fast_ex2(r * fast_lg2(v)) - dr;
            if (act) sp[i * FFR] = o;
        }
        sp += U * FFR;

        // Prefetch chunk c+2 into A (skip on final pair).
        if (c + 2 < NCH) {
            #pragma unroll
            for (int i = 0; i < U; i++) bufA[i] = __ldg(lp + i * FFR);
            lp += U * FFR;
        }

        // Process chunk c+1 from B.
        #pragma unroll
        for (int i = 0; i < U; i++) {
            const float xv = bufB[i];
            m = fmaf(oms, m, s * xv);
            const float e  = fast_ex2(na * fast_lg2(m + PCEN_EPS));
            const float v  = fmaf(xv, e, delta);
            const float o  = fast_ex2(r * fast_lg2(v)) - dr;
            if (act) sp[i * FFR] = o;
        }
        sp += U * FFR;
    }
}

extern "C" void kernel_launch(void* const* d_in, const int* in_sizes, int n_in,
                              void* d_out, int out_size)
{
    const float* x     = (const float*)d_in[0];
    const float* s_p   = (const float*)d_in[1];
    const float* a_p   = (const float*)d_in[2];
    const float* d_p   = (const float*)d_in[3];
    const float* r_p   = (const float*)d_in[4];
    float*       out   = (float*)d_out;

    dim3 grid(16 * NFC);   // 144 blocks
    dim3 block(128);
    pcen_kernel<<<grid, block>>>(x, s_p, a_p, d_p, r_p, out);
}

// round 2
// speedup vs baseline: 1.7318x; 1.7318x over previous
#include <cuda_runtime.h>

// StreamingPCEN: x[B=16, MICS=4, T=2048, F=257] fp32.
// EMA over T per (bm, f) lane, then (x/(M+eps)^alpha + delta)^r - delta^r.
//
// Round 2: T is split into 4 segments of 512. Segments 1-3 warm up the EMA
// over a 384-frame halo (restart error decays by (1-s)^384 ~ 6e-5, well under
// the 1e-3 threshold). Grid = 16 bm-groups x 9 f-chunks x 4 segments = 576
// blocks of 128 threads -> single wave, 4 warps per SMSP (vs 1 before),
// hiding DRAM latency and MUFU chains. r==0.5 takes a sqrt.approx fast path
// (3 MUFU/elem instead of 4). Halo EMA uses a 2-step recurrence to halve the
// serial fma chain.

#define TT    2048
#define FFR   257
#define NFC   9          // ceil(257/32)
#define NSEG  4
#define SEG   512        // TT / NSEG
#define HALO  384        // 12 chunks of 32
#define U     32
#define UHCH  (HALO / U) // 12 halo chunks
#define UMCH  (SEG / U)  // 16 main chunks
#define PCEN_EPS 1e-6f

__device__ __forceinline__ float fast_lg2(float a) {
    float r; asm("lg2.approx.f32 %0, %1;" : "=f"(r) : "f"(a)); return r;
}
__device__ __forceinline__ float fast_ex2(float a) {
    float r; asm("ex2.approx.f32 %0, %1;" : "=f"(r) : "f"(a)); return r;
}
__device__ __forceinline__ float fast_sqrt(float a) {
    float r; asm("sqrt.approx.f32 %0, %1;" : "=f"(r) : "f"(a)); return r;
}

__global__ __launch_bounds__(128, 4)
void pcen_kernel(const float* __restrict__ x,
                 const float* __restrict__ s_p,
                 const float* __restrict__ a_p,
                 const float* __restrict__ d_p,
                 const float* __restrict__ r_p,
                 float* __restrict__ out)
{
    const int seg  = blockIdx.x & 3;           // NSEG = 4
    const int rest = blockIdx.x >> 2;
    const int fc   = rest % NFC;
    const int bg   = rest / NFC;
    const int w    = threadIdx.x >> 5;
    const int lane = threadIdx.x & 31;
    const int bm   = bg * 4 + w;
    const int f    = fc * 32 + lane;
    const bool act = (f < FFR);
    const int fcl  = act ? f : (FFR - 1);      // clamp loads for inactive lanes

    const float s     = __ldg(s_p);
    const float alpha = __ldg(a_p);
    const float delta = __ldg(d_p);
    const float r     = __ldg(r_p);
    const float oms   = 1.0f - s;
    const float na    = -alpha;
    const float c2    = oms * oms;             // (1-s)^2  (2-step halo)
    const float s1    = s * oms;               // s(1-s)
    const bool  use_sqrt = (r == 0.5f);
    const float dr    = use_sqrt ? fast_sqrt(delta)
                                 : fast_ex2(r * fast_lg2(delta));  // delta^r

    const float* base = x + (size_t)bm * TT * FFR;
    const int t0 = seg * SEG;

    float bufA[U], bufB[U];
    float m = 0.0f;

    // ---------------- Halo warm-up (segments 1-3) ----------------
    if (seg != 0) {
        const float* lp = base + (size_t)(t0 - HALO) * FFR + fcl;

        #pragma unroll
        for (int i = 0; i < U; i++) bufA[i] = __ldg(lp + i * FFR);
        lp += U * FFR;

        // Restart: m_init = x[th]; with the 2-step update the first pair then
        // yields m = (1-s)*x[th] + s*x[th+1], matching the exact recurrence
        // restarted at th.
        m = bufA[0];

        #pragma unroll 1
        for (int c = 0; c < UHCH; c += 2) {
            #pragma unroll
            for (int i = 0; i < U; i++) bufB[i] = __ldg(lp + i * FFR);
            lp += U * FFR;

            #pragma unroll
            for (int i = 0; i < U; i += 2) {
                const float inner = fmaf(s1, bufA[i], s * bufA[i + 1]);
                m = fmaf(c2, m, inner);
            }

            if (c + 2 < UHCH) {
                #pragma unroll
                for (int i = 0; i < U; i++) bufA[i] = __ldg(lp + i * FFR);
                lp += U * FFR;
            }

            #pragma unroll
            for (int i = 0; i < U; i += 2) {
                const float inner = fmaf(s1, bufB[i], s * bufB[i + 1]);
                m = fmaf(c2, m, inner);
            }
        }
    }

    // ---------------- Main segment ----------------
    const float* lp = base + (size_t)t0 * FFR + fcl;
    float*       sp = out + (size_t)bm * TT * FFR + (size_t)t0 * FFR + f;

    #pragma unroll
    for (int i = 0; i < U; i++) bufA[i] = __ldg(lp + i * FFR);
    lp += U * FFR;

    if (seg == 0) m = bufA[0];   // M_0 = x_0

    #pragma unroll 1
    for (int c = 0; c < UMCH; c += 2) {
        #pragma unroll
        for (int i = 0; i < U; i++) bufB[i] = __ldg(lp + i * FFR);
        lp += U * FFR;

        if (use_sqrt) {
            #pragma unroll
            for (int i = 0; i < U; i++) {
                const float xv = bufA[i];
                m = fmaf(oms, m, s * xv);
                const float e = fast_ex2(na * fast_lg2(m + PCEN_EPS));
                const float v = fmaf(xv, e, delta);
                const float o = fast_sqrt(v) - dr;
                if (act) sp[i * FFR] = o;
            }
        } else {
            #pragma unroll
            for (int i = 0; i < U; i++) {
                const float xv = bufA[i];
                m = fmaf(oms, m, s * xv);
                const float e = fast_ex2(na * fast_lg2(m + PCEN_EPS));
                const float v = fmaf(xv, e, delta);
                const float o = fast_ex2(r * fast_lg2(v)) - dr;
                if (act) sp[i * FFR] = o;
            }
        }
        sp += U * FFR;

        if (c + 2 < UMCH) {
            #pragma unroll
            for (int i = 0; i < U; i++) bufA[i] = __ldg(lp + i * FFR);
            lp += U * FFR;
        }

        if (use_sqrt) {
            #pragma unroll
            for (int i = 0; i < U; i++) {
                const float xv = bufB[i];
                m = fmaf(oms, m, s * xv);
                const float e = fast_ex2(na * fast_lg2(m + PCEN_EPS));
                const float v = fmaf(xv, e, delta);
                const float o = fast_sqrt(v) - dr;
                if (act) sp[i * FFR] = o;
            }
        } else {
            #pragma unroll
            for (int i = 0; i < U; i++) {
                const float xv = bufB[i];
                m = fmaf(oms, m, s * xv);
                const float e = fast_ex2(na * fast_lg2(m + PCEN_EPS));
                const float v = fmaf(xv, e, delta);
                const float o = fast_ex2(r * fast_lg2(v)) - dr;
                if (act) sp[i * FFR] = o;
            }
        }
        sp += U * FFR;
    }
}

extern "C" void kernel_launch(void* const* d_in, const int* in_sizes, int n_in,
                              void* d_out, int out_size)
{
    const float* x   = (const float*)d_in[0];
    const float* s_p = (const float*)d_in[1];
    const float* a_p = (const float*)d_in[2];
    const float* d_p = (const float*)d_in[3];
    const float* r_p = (const float*)d_in[4];
    float*       out = (float*)d_out;

    dim3 grid(16 * NFC * NSEG);   // 576 blocks, single wave on 148 SMs
    dim3 block(128);
    pcen_kernel<<<grid, block>>>(x, s_p, a_p, d_p, r_p, out);
}